// round 6
// baseline (speedup 1.0000x reference)
#include <cuda_runtime.h>
#include <cstdint>

// Problem constants
#define BATCH      256
#define TREES      64
#define FEAT       16080        // 120*134
#define MASK_W     1000
#define K_TOP      200
#define ROW_F4     (FEAT / 4)   // 4020
#define LIVE_F4    (MASK_W / 4) // 250  (columns [0,1000) hold all nonzeros)
#define NROWS      (BATCH * TREES)   // 16384 rv rows
#define NROWS_ALL  (NROWS + TREES)   // + 64 attention rows = 16448
#define ZSTRIPES   15                 // zero stripes s=1..15 per row
#define NZBLK      (ZSTRIPES * NROWS_ALL)
#define NBLOCKS    (TREES + NZBLK + NROWS_ALL)

// Completion flag for the in-grid topk -> live-multiply dependency.
// Reset to 0 by a cudaMemsetAsync node before every kernel replay.
__device__ int g_topk_done;

// ---------------------------------------------------------------------------
// One fused kernel, 1-D grid, 256 threads/block:
//   bid in [0, 64):            topk block for tree=bid (smem binary-search
//                              threshold selection, exact jax lower-index
//                              tie-break). Writes attention[t, 0:1000),
//                              fences, atomically bumps g_topk_done.
//                              Lowest bids -> wave-1 resident -> guaranteed
//                              forward progress for the spin below.
//   bid in [64, 64+15*16448):  pure zero stripe s=1..15 of a row
//                              (c4 in [s*256, min((s+1)*256, 4020)) ).
//   last 16448 bids:           stripe 0 of each row. rv rows spin until all
//                              64 topk blocks are done (they run in the last
//                              ~6% of the kernel, so the flag is long set),
//                              then out = x * att for c4<250 plus 6 zeros.
//                              attention rows only zero c4 in [250,256).
// ---------------------------------------------------------------------------
__global__ __launch_bounds__(256)
void fused_kernel(const float* __restrict__ x,
                  const float* __restrict__ mask,
                  float*       __restrict__ out)
{
    const int tid = threadIdx.x;
    const int bid = blockIdx.x;

    float* att_base = out + (size_t)NROWS * FEAT;   // attention rows live here

    // ================= topk path =================
    if (bid < TREES) {
        const int t = bid;
        float* att_row = att_base + (size_t)t * FEAT;

        __shared__ unsigned int skey[MASK_W];
        __shared__ float        sval[MASK_W];
        __shared__ int s_cnt, s_cgt, s_ceq;

        // Load + order-preserving float->uint transform
        for (int i = tid; i < MASK_W; i += 256) {
            const float v = mask[t * MASK_W + i];
            sval[i] = v;
            const int s = __float_as_int(v);
            skey[i] = (s < 0) ? ~(unsigned int)s : ((unsigned int)s | 0x80000000u);
        }
        __syncthreads();

        // Register-cache this thread's 4 keys (sentinel 0 never selected:
        // midpoints are >= 1, finite-float keys are > 0)
        unsigned int k[4];
        #pragma unroll
        for (int q = 0; q < 4; ++q) {
            const int i = tid + q * 256;
            k[q] = (i < MASK_W) ? skey[i] : 0u;
        }

        // Binary search: thr = max T with count(key >= T) >= K_TOP
        unsigned int lo = 0u, hi = 0xFFFFFFFFu;
        while (lo < hi) {
            const unsigned int mid = lo + ((hi - lo) >> 1) + 1u;
            int c = 0;
            #pragma unroll
            for (int q = 0; q < 4; ++q) c += (k[q] >= mid);
            if (tid == 0) s_cnt = 0;
            __syncthreads();
            c = __reduce_add_sync(0xFFFFFFFFu, c);
            if ((tid & 31) == 0) atomicAdd(&s_cnt, c);
            __syncthreads();
            const int total = s_cnt;
            __syncthreads();
            if (total >= K_TOP) lo = mid; else hi = mid - 1u;
        }
        const unsigned int thr = lo;

        // Strictly-greater / equal counts
        if (tid == 0) { s_cgt = 0; s_ceq = 0; }
        __syncthreads();
        int cg = 0, ce = 0;
        #pragma unroll
        for (int q = 0; q < 4; ++q) { cg += (k[q] > thr); ce += (k[q] == thr); }
        cg = __reduce_add_sync(0xFFFFFFFFu, cg);
        ce = __reduce_add_sync(0xFFFFFFFFu, ce);
        if ((tid & 31) == 0) { atomicAdd(&s_cgt, cg); atomicAdd(&s_ceq, ce); }
        __syncthreads();
        const int need  = K_TOP - s_cgt;   // equals to accept
        const int eqtot = s_ceq;

        // Write attention[t, 0:1000)
        #pragma unroll
        for (int q = 0; q < 4; ++q) {
            const int i = tid + q * 256;
            if (i < MASK_W) {
                bool sel = (k[q] > thr);
                if (k[q] == thr) {
                    if (need >= eqtot) {
                        sel = true;                 // all ties fit (common case)
                    } else {                        // boundary tie: lowest index wins
                        int r = 0;
                        for (int j = 0; j < i; ++j) r += (skey[j] == thr);
                        sel = (r < need);
                    }
                }
                const float v = sval[i];
                att_row[i] = sel ? (1.0f / (1.0f + expf(-v))) : 0.0f;
            }
        }

        // Publish: all stores visible before flag bump
        __syncthreads();
        __threadfence();
        if (tid == 0) atomicAdd(&g_topk_done, 1);
        return;
    }

    // ================= zero-stripe path =================
    int SB = bid - TREES;
    if (SB < NZBLK) {
        const int row = SB / ZSTRIPES;
        const int s   = 1 + (SB - row * ZSTRIPES);     // 1..15
        const int c4  = s * 256 + tid;
        if (c4 < ROW_F4) {
            float4 z; z.x = 0.f; z.y = 0.f; z.z = 0.f; z.w = 0.f;
            reinterpret_cast<float4*>(out + (size_t)row * FEAT)[c4] = z;
        }
        return;
    }

    // ================= stripe-0 (live) path =================
    const int row = SB - NZBLK;                        // 0 .. 16447
    if (row >= NROWS) {
        // attention row: topk wrote [0,1000); zero only c4 in [250,256)
        if (tid >= LIVE_F4) {
            float4 z; z.x = 0.f; z.y = 0.f; z.z = 0.f; z.w = 0.f;
            reinterpret_cast<float4*>(out + (size_t)row * FEAT)[tid] = z;
        }
        return;
    }

    // rv row: wait for all 64 topk blocks (normally already done — these are
    // the highest bids and execute at the tail of the kernel)
    volatile int* flag = &g_topk_done;
    while (*flag != TREES) { __nanosleep(128); }
    __threadfence();                                   // acquire

    const int t = row & (TREES - 1);
    const int b = row >> 6;
    const int c4 = tid;                                // 0..255

    float4 r;
    if (c4 < LIVE_F4) {
        const float4 xa = reinterpret_cast<const float4*>(x + (size_t)b * FEAT)[c4];
        const float4 aa = __ldcg(reinterpret_cast<const float4*>(att_base + (size_t)t * FEAT) + c4);
        r.x = xa.x * aa.x;
        r.y = xa.y * aa.y;
        r.z = xa.z * aa.z;
        r.w = xa.w * aa.w;
    } else {
        r.x = 0.0f; r.y = 0.0f; r.z = 0.0f; r.w = 0.0f;
    }
    reinterpret_cast<float4*>(out + (size_t)row * FEAT)[c4] = r;
}

// ---------------------------------------------------------------------------
// Launch: memset flag node + one fused kernel
// ---------------------------------------------------------------------------
extern "C" void kernel_launch(void* const* d_in, const int* in_sizes, int n_in,
                              void* d_out, int out_size)
{
    const float* x    = (const float*)d_in[0];   // (256, 120, 134) fp32
    const float* mask = (const float*)d_in[1];   // (64, 1000) fp32
    float* out = (float*)d_out;

    void* flag_ptr = nullptr;
    cudaGetSymbolAddress(&flag_ptr, g_topk_done);
    cudaMemsetAsync(flag_ptr, 0, sizeof(int));

    fused_kernel<<<NBLOCKS, 256>>>(x, mask, out);
}

// round 7
// speedup vs baseline: 1.2511x; 1.2511x over previous
#include <cuda_runtime.h>
#include <cstdint>

// Problem constants
#define BATCH      256
#define TREES      64
#define FEAT       16080        // 120*134
#define MASK_W     1000
#define K_TOP      200
#define ROW_F4     (FEAT / 4)   // 4020
#define LIVE_F4    (MASK_W / 4) // 250  (columns [0,1000) hold all nonzeros)
#define NROWS      (BATCH * TREES)   // 16384 rv rows
#define NROWS_ALL  (NROWS + TREES)   // + 64 attention rows = 16448

// ---------------------------------------------------------------------------
// Kernel A: block-per-tree exact top-200 via __syncthreads_count binary search.
//   1024 threads, one key per thread (tid >= 1000 holds sentinel key 0, which
//   can never be counted: midpoints are >= 1 and finite-float keys are > 0,
//   so thr > 0 always). One barrier-reduction per search iteration.
//   Exact jax lower-index tie-break: equals accepted lowest-index-first via
//   smem rank scan, taken only in the measure-zero boundary-tie case.
//   Writes attention[t, 0:1000) only; rv_kernel zeros the tail.
// ---------------------------------------------------------------------------
__global__ __launch_bounds__(1024)
void topk_kernel(const float* __restrict__ mask, float* __restrict__ att_out)
{
    const int t   = blockIdx.x;
    const int tid = threadIdx.x;

    __shared__ unsigned int skey[1024];

    // Load + order-preserving float->uint transform
    float v = 0.0f;
    unsigned int key = 0u;
    if (tid < MASK_W) {
        v = mask[t * MASK_W + tid];
        const int s = __float_as_int(v);
        key = (s < 0) ? ~(unsigned int)s : ((unsigned int)s | 0x80000000u);
    }
    skey[tid] = key;   // consumed only on the rare tie path; the search-loop
                       // barriers below order this write before any read

    // Binary search: thr = max T with count(key >= T) >= K_TOP (200th largest).
    // lo/hi are block-uniform (derived from the barrier count), so every
    // thread executes the same iterations.
    unsigned int lo = 0u, hi = 0xFFFFFFFFu;
    while (lo < hi) {
        const unsigned int mid = lo + ((hi - lo) >> 1) + 1u;   // upper mid
        const int total = __syncthreads_count(key >= mid);
        if (total >= K_TOP) lo = mid; else hi = mid - 1u;
    }
    const unsigned int thr = lo;

    // Strictly-greater / equal counts (block-uniform results)
    const int cgt = __syncthreads_count(key > thr);
    const int ceq = __syncthreads_count(key == thr);
    const int need = K_TOP - cgt;            // equals to accept (1 <= need <= ceq)

    bool sel = (key > thr);
    if (key == thr) {
        if (need >= ceq) {
            sel = true;                      // all ties fit (common case)
        } else {                             // boundary tie: lowest indices win
            int r = 0;
            for (int j = 0; j < tid; ++j) r += (skey[j] == thr);
            sel = (r < need);
        }
    }

    if (tid < MASK_W) {
        att_out[(size_t)t * FEAT + tid] = sel ? (1.0f / (1.0f + expf(-v))) : 0.0f;
    }
}

// ---------------------------------------------------------------------------
// Kernel B: full-output store stream (round-5 version, UNCHANGED — 139.2us
//   @ 90.6% DRAM, 18 regs; the lean uniform body is load-bearing).
//   grid = (16, 16448), block = 256; each thread stores one float4.
//   Rows [0, 16384): return_value rows — c4 < 250 multiplies x*att (both L2
//   resident), c4 >= 250 stores zeros. Rows [16384, 16448): attention rows —
//   zero only the tail (A already wrote columns [0,1000)).
// ---------------------------------------------------------------------------
__global__ __launch_bounds__(256)
void rv_kernel(const float* __restrict__ x,
               const float* __restrict__ att,
               float*       __restrict__ out)
{
    const int c4  = blockIdx.x * blockDim.x + threadIdx.x;   // float4 column
    if (c4 >= ROW_F4) return;
    const int row = blockIdx.y;

    if (row >= NROWS) {                    // attention row: zero tail only
        if (c4 >= LIVE_F4) {
            float4 z; z.x = 0.f; z.y = 0.f; z.z = 0.f; z.w = 0.f;
            reinterpret_cast<float4*>(out + (size_t)row * FEAT)[c4] = z;
        }
        return;
    }

    const int t = row & (TREES - 1);
    const int b = row >> 6;

    float4 r;
    if (c4 < LIVE_F4) {
        const float4 xa = reinterpret_cast<const float4*>(x   + (size_t)b * FEAT)[c4];
        const float4 aa = reinterpret_cast<const float4*>(att + (size_t)t * FEAT)[c4];
        r.x = xa.x * aa.x;
        r.y = xa.y * aa.y;
        r.z = xa.z * aa.z;
        r.w = xa.w * aa.w;
    } else {
        r.x = 0.0f; r.y = 0.0f; r.z = 0.0f; r.w = 0.0f;
    }
    reinterpret_cast<float4*>(out + (size_t)row * FEAT)[c4] = r;
}

// ---------------------------------------------------------------------------
// Launch
// ---------------------------------------------------------------------------
extern "C" void kernel_launch(void* const* d_in, const int* in_sizes, int n_in,
                              void* d_out, int out_size)
{
    const float* x    = (const float*)d_in[0];   // (256, 120, 134) fp32
    const float* mask = (const float*)d_in[1];   // (64, 1000) fp32

    float* out = (float*)d_out;
    float* att_out = out + (size_t)NROWS * FEAT; // (64, 16080) appended

    // A) block-per-tree exact top-200 -> attention[t, 0:1000)
    topk_kernel<<<TREES, 1024>>>(mask, att_out);

    // B) one contiguous store stream for the whole output
    dim3 gridB(16, NROWS_ALL);
    rv_kernel<<<gridB, 256>>>(x, att_out, out);
}

// round 9
// speedup vs baseline: 1.2513x; 1.0002x over previous
#include <cuda_runtime.h>
#include <cstdint>

// Problem constants
#define BATCH      256
#define TREES      64
#define FEAT       16080        // 120*134
#define MASK_W     1000
#define K_TOP      200
#define ROW_F4     (FEAT / 4)   // 4020
#define LIVE_F4    (MASK_W / 4) // 250  (columns [0,1000) hold all nonzeros)
#define NROWS      (BATCH * TREES)   // 16384 rv rows
#define NROWS_ALL  (NROWS + TREES)   // + 64 attention rows = 16448

// ---------------------------------------------------------------------------
// Kernel A: block-per-tree exact top-200 via __syncthreads_count binary search.
//   (Round-7 version, UNCHANGED — gap to store kernel is at the launch-
//   overhead floor, ~3us.)
// ---------------------------------------------------------------------------
__global__ __launch_bounds__(1024)
void topk_kernel(const float* __restrict__ mask, float* __restrict__ att_out)
{
    const int t   = blockIdx.x;
    const int tid = threadIdx.x;

    __shared__ unsigned int skey[1024];

    // Load + order-preserving float->uint transform
    float v = 0.0f;
    unsigned int key = 0u;
    if (tid < MASK_W) {
        v = mask[t * MASK_W + tid];
        const int s = __float_as_int(v);
        key = (s < 0) ? ~(unsigned int)s : ((unsigned int)s | 0x80000000u);
    }
    skey[tid] = key;   // consumed only on the rare tie path; the search-loop
                       // barriers below order this write before any read

    // Binary search: thr = max T with count(key >= T) >= K_TOP (200th largest).
    unsigned int lo = 0u, hi = 0xFFFFFFFFu;
    while (lo < hi) {
        const unsigned int mid = lo + ((hi - lo) >> 1) + 1u;   // upper mid
        const int total = __syncthreads_count(key >= mid);
        if (total >= K_TOP) lo = mid; else hi = mid - 1u;
    }
    const unsigned int thr = lo;

    // Strictly-greater / equal counts (block-uniform results)
    const int cgt = __syncthreads_count(key > thr);
    const int ceq = __syncthreads_count(key == thr);
    const int need = K_TOP - cgt;            // equals to accept (1 <= need <= ceq)

    bool sel = (key > thr);
    if (key == thr) {
        if (need >= ceq) {
            sel = true;                      // all ties fit (common case)
        } else {                             // boundary tie: lowest indices win
            int r = 0;
            for (int j = 0; j < tid; ++j) r += (skey[j] == thr);
            sel = (r < need);
        }
    }

    if (tid < MASK_W) {
        att_out[(size_t)t * FEAT + tid] = sel ? (1.0f / (1.0f + expf(-v))) : 0.0f;
    }
}

// ---------------------------------------------------------------------------
// Kernel B: full-output store stream, 4 independent float4 stores per thread.
//   grid = (4, 16448), block = 256. base = bx*256+tid in [0,1024); the thread
//   stores columns {base, base+1024, base+2048, base+3072} of its row
//   (the +3072 store is predicated off for base >= 948 since ROW_F4 = 4020).
//   Live multiply only at base < 250 (bx == 0); x (1 MB) and att (256 KB)
//   stay L2-resident. Front-batched stores quadruple per-warp store MLP and
//   cut block count 4x vs the 1-store version.
//   Rows [16384, 16448) are attention rows: skip base < 250 (topk wrote them).
// ---------------------------------------------------------------------------
__global__ __launch_bounds__(256)
void rv_kernel(const float* __restrict__ x,
               const float* __restrict__ att,
               float*       __restrict__ out)
{
    const int tid  = threadIdx.x;
    const int base = blockIdx.x * 256 + tid;                 // 0 .. 1023
    const int row  = blockIdx.y;

    float4* dst = reinterpret_cast<float4*>(out + (size_t)row * FEAT);
    float4 z; z.x = 0.f; z.y = 0.f; z.z = 0.f; z.w = 0.f;

    if (row >= NROWS) {                    // attention row: zero tail only
        if (base >= LIVE_F4) dst[base] = z;
        dst[base + 1024] = z;
        dst[base + 2048] = z;
        if (base + 3072 < ROW_F4) dst[base + 3072] = z;
        return;
    }

    const int t = row & (TREES - 1);
    const int b = row >> 6;

    float4 r = z;
    if (base < LIVE_F4) {
        const float4 xa = reinterpret_cast<const float4*>(x   + (size_t)b * FEAT)[base];
        const float4 aa = reinterpret_cast<const float4*>(att + (size_t)t * FEAT)[base];
        r.x = xa.x * aa.x;
        r.y = xa.y * aa.y;
        r.z = xa.z * aa.z;
        r.w = xa.w * aa.w;
    }
    dst[base]        = r;
    dst[base + 1024] = z;
    dst[base + 2048] = z;
    if (base + 3072 < ROW_F4) dst[base + 3072] = z;
}

// ---------------------------------------------------------------------------
// Launch
// ---------------------------------------------------------------------------
extern "C" void kernel_launch(void* const* d_in, const int* in_sizes, int n_in,
                              void* d_out, int out_size)
{
    const float* x    = (const float*)d_in[0];   // (256, 120, 134) fp32
    const float* mask = (const float*)d_in[1];   // (64, 1000) fp32

    float* out = (float*)d_out;
    float* att_out = out + (size_t)NROWS * FEAT; // (64, 16080) appended

    // A) block-per-tree exact top-200 -> attention[t, 0:1000)
    topk_kernel<<<TREES, 1024>>>(mask, att_out);

    // B) one contiguous store stream for the whole output, 4 stores/thread
    dim3 gridB(4, NROWS_ALL);
    rv_kernel<<<gridB, 256>>>(x, att_out, out);
}

// round 10
// speedup vs baseline: 1.2929x; 1.0332x over previous
#include <cuda_runtime.h>
#include <cstdint>

// Problem constants
#define BATCH      256
#define TREES      64
#define FEAT       16080        // 120*134
#define MASK_W     1000
#define K_TOP      200
#define ROW_F4     (FEAT / 4)   // 4020
#define LIVE_F4    (MASK_W / 4) // 250  (columns [0,1000) hold all nonzeros)
#define NROWS      (BATCH * TREES)   // 16384 rv rows
#define NROWS_ALL  (NROWS + TREES)   // + 64 attention rows = 16448

// ---------------------------------------------------------------------------
// Kernel A: block-per-tree exact top-200 via __syncthreads_count binary search.
//   Triggers programmatic launch completion at entry so the store kernel's
//   grid launches immediately and overlaps this one.
// ---------------------------------------------------------------------------
__global__ __launch_bounds__(1024)
void topk_kernel(const float* __restrict__ mask, float* __restrict__ att_out)
{
    // Let the dependent rv_kernel grid begin launching now; its att-reading
    // blocks still wait for this grid's completion via
    // cudaGridDependencySynchronize().
    cudaTriggerProgrammaticLaunchCompletion();

    const int t   = blockIdx.x;
    const int tid = threadIdx.x;

    __shared__ unsigned int skey[1024];

    // Load + order-preserving float->uint transform
    float v = 0.0f;
    unsigned int key = 0u;
    if (tid < MASK_W) {
        v = mask[t * MASK_W + tid];
        const int s = __float_as_int(v);
        key = (s < 0) ? ~(unsigned int)s : ((unsigned int)s | 0x80000000u);
    }
    skey[tid] = key;   // consumed only on the rare tie path; the search-loop
                       // barriers below order this write before any read

    // Binary search: thr = max T with count(key >= T) >= K_TOP (200th largest).
    // Sentinel key 0 (tid >= 1000) is never counted: midpoints are >= 1 and
    // finite-float keys are > 0.
    unsigned int lo = 0u, hi = 0xFFFFFFFFu;
    while (lo < hi) {
        const unsigned int mid = lo + ((hi - lo) >> 1) + 1u;   // upper mid
        const int total = __syncthreads_count(key >= mid);
        if (total >= K_TOP) lo = mid; else hi = mid - 1u;
    }
    const unsigned int thr = lo;

    // Strictly-greater / equal counts (block-uniform results)
    const int cgt = __syncthreads_count(key > thr);
    const int ceq = __syncthreads_count(key == thr);
    const int need = K_TOP - cgt;            // equals to accept (1 <= need <= ceq)

    bool sel = (key > thr);
    if (key == thr) {
        if (need >= ceq) {
            sel = true;                      // all ties fit (common case)
        } else {                             // boundary tie: lowest indices win
            int r = 0;
            for (int j = 0; j < tid; ++j) r += (skey[j] == thr);
            sel = (r < need);
        }
    }

    if (tid < MASK_W) {
        att_out[(size_t)t * FEAT + tid] = sel ? (1.0f / (1.0f + expf(-v))) : 0.0f;
    }
}

// ---------------------------------------------------------------------------
// Kernel B: full-output store stream, 4 independent float4 stores per thread
//   (round-9 version + PDL dependency sync).
//   grid = (4, 16448), block = 256. base = bx*256+tid in [0,1024); thread
//   stores columns {base, base+1024, base+2048, base+3072} of its row.
//   Only bx==0 rv-row blocks read attention, so only they execute
//   cudaGridDependencySynchronize(); the other 75% of blocks stream zero
//   stores with no extra instructions — the store wave stays clean.
// ---------------------------------------------------------------------------
__global__ __launch_bounds__(256)
void rv_kernel(const float* __restrict__ x,
               const float* __restrict__ att,
               float*       __restrict__ out)
{
    const int tid  = threadIdx.x;
    const int base = blockIdx.x * 256 + tid;                 // 0 .. 1023
    const int row  = blockIdx.y;

    float4* dst = reinterpret_cast<float4*>(out + (size_t)row * FEAT);
    float4 z; z.x = 0.f; z.y = 0.f; z.z = 0.f; z.w = 0.f;

    if (row >= NROWS) {                    // attention row: zero tail only
        if (base >= LIVE_F4) dst[base] = z;
        dst[base + 1024] = z;
        dst[base + 2048] = z;
        if (base + 3072 < ROW_F4) dst[base + 3072] = z;
        return;
    }

    const int t = row & (TREES - 1);
    const int b = row >> 6;

    float4 r = z;
    if (base < LIVE_F4) {
        // Wait for topk_kernel's attention writes to be visible.
        cudaGridDependencySynchronize();
        const float4 xa = reinterpret_cast<const float4*>(x   + (size_t)b * FEAT)[base];
        const float4 aa = reinterpret_cast<const float4*>(att + (size_t)t * FEAT)[base];
        r.x = xa.x * aa.x;
        r.y = xa.y * aa.y;
        r.z = xa.z * aa.z;
        r.w = xa.w * aa.w;
    }
    dst[base]        = r;
    dst[base + 1024] = z;
    dst[base + 2048] = z;
    if (base + 3072 < ROW_F4) dst[base + 3072] = z;
}

// ---------------------------------------------------------------------------
// Launch: topk, then rv with programmatic stream serialization (PDL) so the
// rv grid launches and its independent blocks run while topk is in flight.
// ---------------------------------------------------------------------------
extern "C" void kernel_launch(void* const* d_in, const int* in_sizes, int n_in,
                              void* d_out, int out_size)
{
    const float* x    = (const float*)d_in[0];   // (256, 120, 134) fp32
    const float* mask = (const float*)d_in[1];   // (64, 1000) fp32

    float* out = (float*)d_out;
    float* att_out = out + (size_t)NROWS * FEAT; // (64, 16080) appended

    // A) block-per-tree exact top-200 -> attention[t, 0:1000)
    topk_kernel<<<TREES, 1024>>>(mask, att_out);

    // B) full-output store stream, launched with PDL overlap
    cudaLaunchConfig_t cfg = {};
    cfg.gridDim  = dim3(4, NROWS_ALL, 1);
    cfg.blockDim = dim3(256, 1, 1);
    cfg.dynamicSmemBytes = 0;
    cudaLaunchAttribute attr[1];
    attr[0].id = cudaLaunchAttributeProgrammaticStreamSerialization;
    attr[0].val.programmaticStreamSerializationAllowed = 1;
    cfg.attrs = attr;
    cfg.numAttrs = 1;
    cudaLaunchKernelEx(&cfg, rv_kernel, x, (const float*)att_out, out);
}